// round 11
// baseline (speedup 1.0000x reference)
#include <cuda_runtime.h>
#include <cuda.h>
#include <cuda_bf16.h>
#include <cstdint>

namespace {

constexpr int   HW    = 36864;        // 192*192
constexpr float SCALE = 0.17677669529663687f;  // 1/sqrt(32)

// dynamic smem layout (float/word units)
constexpr int RAW  = 0;      // 2048 words: TMA staging (Q,K,V) -> mask rows 0..31
constexpr int TQH  = 2048;   // Q hi tile: 64 x 20  -> mask rows 32..63 span [2048,4096)
constexpr int TQL  = 3328;
constexpr int TKH  = 4608;
constexpr int TKL  = 5888;
constexpr int TVH  = 7168;   // V hi tile: 32 x 36 (1148)
constexpr int TVL  = 8316;
constexpr int MBAR = 9464;   // 2 words
constexpr int SMEM_BYTES = 9466 * 4;  // 37864 B -> 6 CTAs/SM

__device__ __forceinline__ uint32_t s2u(const void* p) {
  uint32_t a;
  asm("{ .reg .u64 t; cvta.to.shared.u64 t, %1; cvt.u32.u64 %0, t; }" : "=r"(a) : "l"(p));
  return a;
}
__device__ __forceinline__ uint32_t pack2(float lo, float hi) {
  uint32_t r;
  asm("cvt.rn.bf16x2.f32 %0, %1, %2;" : "=r"(r) : "f"(hi), "f"(lo));
  return r;
}
__device__ __forceinline__ float bfv(float f) {
  return __bfloat162float(__float2bfloat16_rn(f));
}
__device__ __forceinline__ void mma_bf16(float* c, const uint32_t* a,
                                         uint32_t b0, uint32_t b1) {
  asm volatile(
      "mma.sync.aligned.m16n8k16.row.col.f32.bf16.bf16.f32 "
      "{%0,%1,%2,%3}, {%4,%5,%6,%7}, {%8,%9}, {%0,%1,%2,%3};"
      : "+f"(c[0]), "+f"(c[1]), "+f"(c[2]), "+f"(c[3])
      : "r"(a[0]), "r"(a[1]), "r"(a[2]), "r"(a[3]), "r"(b0), "r"(b1));
}
__device__ __forceinline__ int qkw(int r, int w) {
  return r * 20 + (w ^ (((r >> 3) & 3) << 2));
}
__device__ __forceinline__ float felem(float4 a, int j) {
  return (j == 0) ? a.x : (j == 1) ? a.y : (j == 2) ? a.z : a.w;
}
__device__ __forceinline__ void bar_init(uint32_t bar, uint32_t cnt) {
  asm volatile("mbarrier.init.shared.b64 [%0], %1;" :: "r"(bar), "r"(cnt) : "memory");
}
__device__ __forceinline__ void bar_expect(uint32_t bar, uint32_t bytes) {
  asm volatile("mbarrier.arrive.expect_tx.shared.b64 _, [%0], %1;"
               :: "r"(bar), "r"(bytes) : "memory");
}
__device__ __forceinline__ void bar_wait(uint32_t bar, uint32_t parity) {
  uint32_t done;
  asm volatile(
      "{\n\t.reg .pred p;\n\t"
      "mbarrier.try_wait.parity.acquire.cta.shared::cta.b64 p, [%1], %2;\n\t"
      "selp.b32 %0, 1, 0, p;\n\t}"
      : "=r"(done) : "r"(bar), "r"(parity) : "memory");
  if (!done) {
    asm volatile(
        "{\n\t.reg .pred P1;\n\t"
        "W_%=:\n\t"
        "mbarrier.try_wait.parity.acquire.cta.shared::cta.b64 P1, [%0], %1, 0x989680;\n\t"
        "@P1 bra.uni D_%=;\n\t"
        "bra.uni W_%=;\n\t"
        "D_%=:\n\t}"
        :: "r"(bar), "r"(parity) : "memory");
  }
}
__device__ __forceinline__ void tma3d(uint32_t dst, const CUtensorMap* map,
                                      int x, int y, int z, uint32_t bar) {
  asm volatile(
      "cp.async.bulk.tensor.3d.shared::cta.global.tile.mbarrier::complete_tx::bytes "
      "[%0], [%1, {%2, %3, %4}], [%5];"
      :: "r"(dst), "l"(map), "r"(x), "r"(y), "r"(z), "r"(bar) : "memory");
}
__device__ __forceinline__ void tma3d_store(const CUtensorMap* map,
                                            int x, int y, int z, uint32_t src) {
  asm volatile(
      "cp.async.bulk.tensor.3d.global.shared::cta.tile.bulk_group "
      "[%0, {%1, %2, %3}], [%4];"
      :: "l"(map), "r"(x), "r"(y), "r"(z), "r"(src) : "memory");
}

}  // namespace

__global__ __launch_bounds__(128, 6) void winattn_tma5(
    const __grid_constant__ CUtensorMap mapQ,
    const __grid_constant__ CUtensorMap mapKV,
    const __grid_constant__ CUtensorMap mapO,
    const float* __restrict__ mask) {
  extern __shared__ float dyn[];
  float* __restrict__ raw = dyn + RAW;
  uint32_t* __restrict__ sm = (uint32_t*)dyn;   // tiles addressed by absolute word offset

  const int tid = threadIdx.x;
  const int wid = tid >> 5;
  const int lid = tid & 31;

  // block decode: 48 consecutive CTAs (8 b x 6 d) share one mask window (L2 reuse)
  const int blk = blockIdx.x;
  const int win = blk / 48;
  const int rem = blk % 48;
  const int b = rem / 6;
  const int d = rem % 6;
  const int u = win / 24;
  const int v = win % 24;
  const int zc = b * 192 + d * 32;

  const uint32_t mbar = s2u(dyn + MBAR);
  const uint32_t rawA = s2u(raw);
  if (tid == 0) bar_init(mbar, 1);
  __syncthreads();

  // ---------------- phase 1: Q -> raw, convert to TQH/TQL ----------------
  if (tid == 0) {
    bar_expect(mbar, 8192);
    tma3d(rawA, &mapQ, v * 8, u * 8, zc, mbar);
  }
  bar_wait(mbar, 0);
#pragma unroll
  for (int it = 0; it < 2; it++) {
    const int p  = it * 128 + tid;       // 0..255
    const int cw = p >> 4;               // word index = ci/2 (0..15)
    const int h  = (p >> 1) & 7;
    const int wq = p & 1;
    const int n0 = h * 8 + wq * 4;
    const int ro = (2 * cw) * 64 + h * 8 + wq * 4;
    const float4 a0 = *(const float4*)(raw + ro);
    const float4 a1 = *(const float4*)(raw + ro + 64);
#pragma unroll
    for (int j = 0; j < 4; j++) {
      const float f0 = felem(a0, j), f1 = felem(a1, j);
      const int w = qkw(n0 + j, cw);
      sm[TQH + w] = pack2(f0, f1);
      sm[TQL + w] = pack2(f0 - bfv(f0), f1 - bfv(f1));
    }
  }
  __syncthreads();

  // ---------------- phase 2: K -> raw, convert to TKH/TKL ----------------
  if (tid == 0) {
    bar_expect(mbar, 8192);
    tma3d(rawA, &mapKV, v * 8, u * 8, zc, mbar);
  }
  bar_wait(mbar, 1);
#pragma unroll
  for (int it = 0; it < 2; it++) {
    const int p  = it * 128 + tid;
    const int cw = p >> 4;
    const int h  = (p >> 1) & 7;
    const int wq = p & 1;
    const int n0 = h * 8 + wq * 4;
    const int ro = (2 * cw) * 64 + h * 8 + wq * 4;
    const float4 a0 = *(const float4*)(raw + ro);
    const float4 a1 = *(const float4*)(raw + ro + 64);
#pragma unroll
    for (int j = 0; j < 4; j++) {
      const float f0 = felem(a0, j), f1 = felem(a1, j);
      const int w = qkw(n0 + j, cw);
      sm[TKH + w] = pack2(f0, f1);
      sm[TKL + w] = pack2(f0 - bfv(f0), f1 - bfv(f1));
    }
  }
  __syncthreads();

  // ---------------- phase 3: V -> raw, convert to TVH/TVL ----------------
  if (tid == 0) {
    bar_expect(mbar, 8192);
    tma3d(rawA, &mapKV, v * 8, u * 8, 1536 + zc, mbar);
  }
  bar_wait(mbar, 0);
#pragma unroll
  for (int it = 0; it < 4; it++) {
    const int p  = it * 128 + tid;       // 0..511
    const int ci = p >> 4;
    const int h  = (p >> 1) & 7;
    const int wq = p & 1;
    const int n0 = h * 8 + wq * 4;
    const float4 a = *(const float4*)(raw + ci * 64 + h * 8 + wq * 4);
    uint2 hp, lp;
    hp.x = pack2(a.x, a.y);
    hp.y = pack2(a.z, a.w);
    lp.x = pack2(a.x - bfv(a.x), a.y - bfv(a.y));
    lp.y = pack2(a.z - bfv(a.z), a.w - bfv(a.w));
    *(uint2*)&sm[TVH + ci * 36 + (n0 >> 1)] = hp;
    *(uint2*)&sm[TVL + ci * 36 + (n0 >> 1)] = lp;
  }
  __syncthreads();

  const int g  = lid >> 2;   // 0..7
  const int t  = lid & 3;    // 0..3
  const int m0 = wid * 16;

  // ================= A-fragments (before Q tiles are overwritten) ===============
  uint32_t aqh[2][4], aql[2][4];
#pragma unroll
  for (int ks = 0; ks < 2; ks++) {
    aqh[ks][0] = sm[TQH + qkw(m0 + g,     ks * 8 + t)];
    aqh[ks][1] = sm[TQH + qkw(m0 + g + 8, ks * 8 + t)];
    aqh[ks][2] = sm[TQH + qkw(m0 + g,     ks * 8 + 4 + t)];
    aqh[ks][3] = sm[TQH + qkw(m0 + g + 8, ks * 8 + 4 + t)];
    aql[ks][0] = sm[TQL + qkw(m0 + g,     ks * 8 + t)];
    aql[ks][1] = sm[TQL + qkw(m0 + g + 8, ks * 8 + t)];
    aql[ks][2] = sm[TQL + qkw(m0 + g,     ks * 8 + 4 + t)];
    aql[ks][3] = sm[TQL + qkw(m0 + g + 8, ks * 8 + 4 + t)];
  }
  __syncthreads();   // all A-fragments read before mask staging overwrites Q tiles

  // ===== CTA-dense fp32 mask staging: rows 0..31 -> raw, rows 32..63 -> Q tiles ==
  // word(r, o) = base(r) + (o ^ 2*(r&7)); XOR makes softmax float2 reads conflict-free
  {
    const float2* __restrict__ mg2 = (const float2*)(mask + win * 4096);
#pragma unroll
    for (int it = 0; it < 16; it++) {
      const int p = it * 128 + tid;      // float2 id 0..2047
      const int row = p >> 5;
      const int o2 = (p & 31) * 2;
      const float2 m = mg2[p];
      const int base = (row < 32) ? (row * 64) : (2048 + (row - 32) * 64);
      *(float2*)&dyn[base + (o2 ^ (2 * (row & 7)))] = m;
    }
  }
  __syncthreads();

  // ================= QK^T : warp owns rows m0..m0+15 =============================
  float c[8][4];
#pragma unroll
  for (int j = 0; j < 8; j++)
#pragma unroll
    for (int i = 0; i < 4; i++) c[j][i] = 0.f;

#pragma unroll
  for (int j = 0; j < 8; j++) {          // n-tile: cols 8j..8j+7
    const int rb = j * 8 + g;
#pragma unroll
    for (int ks = 0; ks < 2; ks++) {
      const uint32_t bh0 = sm[TKH + qkw(rb, ks * 8 + t)];
      const uint32_t bh1 = sm[TKH + qkw(rb, ks * 8 + 4 + t)];
      const uint32_t bl0 = sm[TKL + qkw(rb, ks * 8 + t)];
      const uint32_t bl1 = sm[TKL + qkw(rb, ks * 8 + 4 + t)];
      mma_bf16(c[j], aqh[ks], bh0, bh1);
      mma_bf16(c[j], aqh[ks], bl0, bl1);
      mma_bf16(c[j], aql[ks], bh0, bh1);
    }
  }

  // ================= softmax (rows m0+g, m0+g+8; swizzled fp32 mask) =============
  const int r0 = m0 + g;
  const float* __restrict__ mrow =
      dyn + ((wid < 2) ? (r0 * 64) : (2048 + (r0 - 32) * 64));
  const int sw = 2 * g;
  float sum0 = 0.f, sum1 = 0.f;
#pragma unroll
  for (int j = 0; j < 8; j++) {
    const int o = (8 * j + 2 * t) ^ sw;
    const float2 mv0 = *(const float2*)(mrow + o);
    const float2 mv1 = *(const float2*)(mrow + 512 + o);
    float e;
    e = __expf(fmaf(c[j][0], SCALE, mv0.x)); c[j][0] = e; sum0 += e;
    e = __expf(fmaf(c[j][1], SCALE, mv0.y)); c[j][1] = e; sum0 += e;
    e = __expf(fmaf(c[j][2], SCALE, mv1.x)); c[j][2] = e; sum1 += e;
    e = __expf(fmaf(c[j][3], SCALE, mv1.y)); c[j][3] = e; sum1 += e;
  }
  sum0 += __shfl_xor_sync(0xffffffffu, sum0, 1);
  sum0 += __shfl_xor_sync(0xffffffffu, sum0, 2);
  sum1 += __shfl_xor_sync(0xffffffffu, sum1, 1);
  sum1 += __shfl_xor_sync(0xffffffffu, sum1, 2);
  const float inv0 = 1.0f / sum0;
  const float inv1 = 1.0f / sum1;

  // P fragments (S accumulator layout == PV A-fragment layout), hi/lo split
  uint32_t aph[4][4], apl[4][4];
#pragma unroll
  for (int ks = 0; ks < 4; ks++) {
    const float* p0 = c[2 * ks];
    const float* p1 = c[2 * ks + 1];
    aph[ks][0] = pack2(p0[0], p0[1]);
    aph[ks][1] = pack2(p0[2], p0[3]);
    aph[ks][2] = pack2(p1[0], p1[1]);
    aph[ks][3] = pack2(p1[2], p1[3]);
    apl[ks][0] = pack2(p0[0] - bfv(p0[0]), p0[1] - bfv(p0[1]));
    apl[ks][1] = pack2(p0[2] - bfv(p0[2]), p0[3] - bfv(p0[3]));
    apl[ks][2] = pack2(p1[0] - bfv(p1[0]), p1[1] - bfv(p1[1]));
    apl[ks][3] = pack2(p1[2] - bfv(p1[2]), p1[3] - bfv(p1[3]));
  }
  __syncthreads();   // all warps done with mask/Q region before sO reuses it

  // ================= O = P V =====================================================
  float o[4][4];
#pragma unroll
  for (int jn = 0; jn < 4; jn++)
#pragma unroll
    for (int i = 0; i < 4; i++) o[jn][i] = 0.f;

#pragma unroll
  for (int jn = 0; jn < 4; jn++) {       // channel tile 8jn..8jn+7
    const int rv = (jn * 8 + g) * 36;
#pragma unroll
    for (int ks = 0; ks < 4; ks++) {     // key step 16ks..16ks+15
      const uint32_t bh0 = sm[TVH + rv + ks * 8 + t];
      const uint32_t bh1 = sm[TVH + rv + ks * 8 + 4 + t];
      const uint32_t bl0 = sm[TVL + rv + ks * 8 + t];
      const uint32_t bl1 = sm[TVL + rv + ks * 8 + 4 + t];
      mma_bf16(o[jn], aph[ks], bh0, bh1);
      mma_bf16(o[jn], aph[ks], bl0, bl1);
      mma_bf16(o[jn], apl[ks], bh0, bh1);
    }
  }

  // ===== stage O dense [c][h][w] fp32 (plain layout, TMA store source) ===========
  float* __restrict__ sO = dyn + TQH;    // words [2048..4096), mask/Q dead
#pragma unroll
  for (int jn = 0; jn < 4; jn++) {
    const int ch = jn * 8 + 2 * t;
#pragma unroll
    for (int bb = 0; bb < 2; bb++) {
      sO[(ch + bb) * 64 + m0 + g]     = o[jn][bb] * inv0;
      sO[(ch + bb) * 64 + m0 + g + 8] = o[jn][2 + bb] * inv1;
    }
  }
  __syncthreads();

  // ================= TMA store O =================================================
  if (tid == 0) {
    asm volatile("fence.proxy.async.shared::cta;" ::: "memory");
    tma3d_store(&mapO, v * 8, u * 8, zc, s2u(sO));
    asm volatile("cp.async.bulk.commit_group;" ::: "memory");
    asm volatile("cp.async.bulk.wait_group 0;" ::: "memory");
  }
}

typedef CUresult (*EncodeFn)(CUtensorMap*, CUtensorMapDataType, cuuint32_t, void*,
                             const cuuint64_t*, const cuuint64_t*, const cuuint32_t*,
                             const cuuint32_t*, CUtensorMapInterleave, CUtensorMapSwizzle,
                             CUtensorMapL2promotion, CUtensorMapFloatOOBfill);

extern "C" void kernel_launch(void* const* d_in, const int* in_sizes, int n_in,
                              void* d_out, int out_size) {
  const float* kv = nullptr;
  const float* q = nullptr;
  const float* mask = nullptr;
  for (int i = 0; i < n_in; i++) {
    if (in_sizes[i] == 113246208) kv = (const float*)d_in[i];
    else if (in_sizes[i] == 56623104) q = (const float*)d_in[i];
    else if (in_sizes[i] == 2359296) mask = (const float*)d_in[i];
  }
  if (!kv)   kv   = (const float*)d_in[0];
  if (!q)    q    = (const float*)d_in[1];
  if (!mask) mask = (const float*)d_in[2];

  EncodeFn encode = nullptr;
  cudaDriverEntryPointQueryResult qres;
  cudaGetDriverEntryPoint("cuTensorMapEncodeTiled", (void**)&encode,
                          cudaEnableDefault, &qres);

  cuuint64_t strides[2] = {192 * 4ull, (cuuint64_t)HW * 4ull};
  cuuint32_t box[3]     = {8, 8, 32};
  cuuint32_t es[3]      = {1, 1, 1};

  CUtensorMap mapQ{}, mapKV{}, mapO{};
  {
    cuuint64_t dims[3] = {192, 192, 1536};
    encode(&mapQ, CU_TENSOR_MAP_DATA_TYPE_FLOAT32, 3, (void*)q,
           dims, strides, box, es,
           CU_TENSOR_MAP_INTERLEAVE_NONE, CU_TENSOR_MAP_SWIZZLE_NONE,
           CU_TENSOR_MAP_L2_PROMOTION_L2_128B, CU_TENSOR_MAP_FLOAT_OOB_FILL_NONE);
  }
  {
    cuuint64_t dims[3] = {192, 192, 3072};
    encode(&mapKV, CU_TENSOR_MAP_DATA_TYPE_FLOAT32, 3, (void*)kv,
           dims, strides, box, es,
           CU_TENSOR_MAP_INTERLEAVE_NONE, CU_TENSOR_MAP_SWIZZLE_NONE,
           CU_TENSOR_MAP_L2_PROMOTION_L2_128B, CU_TENSOR_MAP_FLOAT_OOB_FILL_NONE);
  }
  {
    cuuint64_t dims[3] = {192, 192, 1536};
    encode(&mapO, CU_TENSOR_MAP_DATA_TYPE_FLOAT32, 3, d_out,
           dims, strides, box, es,
           CU_TENSOR_MAP_INTERLEAVE_NONE, CU_TENSOR_MAP_SWIZZLE_NONE,
           CU_TENSOR_MAP_L2_PROMOTION_L2_128B, CU_TENSOR_MAP_FLOAT_OOB_FILL_NONE);
  }

  cudaFuncSetAttribute(winattn_tma5, cudaFuncAttributeMaxDynamicSharedMemorySize,
                       SMEM_BYTES);
  winattn_tma5<<<27648, 128, SMEM_BYTES>>>(mapQ, mapKV, mapO, mask);
}

// round 13
// speedup vs baseline: 1.0905x; 1.0905x over previous
#include <cuda_runtime.h>
#include <cuda.h>
#include <cuda_bf16.h>
#include <cstdint>

namespace {

constexpr int   HW    = 36864;        // 192*192
constexpr float SCALE = 0.17677669529663687f;  // 1/sqrt(32)

// dynamic smem layout (float/word units)
constexpr int RAW  = 0;      // 2048 words: TMA staging buffer (Q, then K, then V)
constexpr int TQH  = 2048;   // Q hi tile: 64 x 20
constexpr int TQL  = 3328;
constexpr int TKH  = 4608;
constexpr int TKL  = 5888;
constexpr int TVH  = 7168;   // V hi tile: 32 x 36 (1148)
constexpr int TVL  = 8316;
constexpr int MBAR = 9464;   // 2 words
constexpr int SMEM_BYTES = 9466 * 4;  // 37864 B -> 6 CTAs/SM

__device__ __forceinline__ uint32_t s2u(const void* p) {
  uint32_t a;
  asm("{ .reg .u64 t; cvta.to.shared.u64 t, %1; cvt.u32.u64 %0, t; }" : "=r"(a) : "l"(p));
  return a;
}
__device__ __forceinline__ uint32_t pack2(float lo, float hi) {
  uint32_t r;
  asm("cvt.rn.bf16x2.f32 %0, %1, %2;" : "=r"(r) : "f"(hi), "f"(lo));
  return r;
}
__device__ __forceinline__ float bfv(float f) {
  return __bfloat162float(__float2bfloat16_rn(f));
}
__device__ __forceinline__ void mma_bf16(float* c, const uint32_t* a,
                                         uint32_t b0, uint32_t b1) {
  asm volatile(
      "mma.sync.aligned.m16n8k16.row.col.f32.bf16.bf16.f32 "
      "{%0,%1,%2,%3}, {%4,%5,%6,%7}, {%8,%9}, {%0,%1,%2,%3};"
      : "+f"(c[0]), "+f"(c[1]), "+f"(c[2]), "+f"(c[3])
      : "r"(a[0]), "r"(a[1]), "r"(a[2]), "r"(a[3]), "r"(b0), "r"(b1));
}
__device__ __forceinline__ int qkw(int r, int w) {
  return r * 20 + (w ^ (((r >> 3) & 3) << 2));
}
__device__ __forceinline__ float felem(float4 a, int j) {
  return (j == 0) ? a.x : (j == 1) ? a.y : (j == 2) ? a.z : a.w;
}
__device__ __forceinline__ void bar_init(uint32_t bar, uint32_t cnt) {
  asm volatile("mbarrier.init.shared.b64 [%0], %1;" :: "r"(bar), "r"(cnt) : "memory");
}
__device__ __forceinline__ void bar_expect(uint32_t bar, uint32_t bytes) {
  asm volatile("mbarrier.arrive.expect_tx.shared.b64 _, [%0], %1;"
               :: "r"(bar), "r"(bytes) : "memory");
}
__device__ __forceinline__ void bar_wait(uint32_t bar, uint32_t parity) {
  uint32_t done;
  asm volatile(
      "{\n\t.reg .pred p;\n\t"
      "mbarrier.try_wait.parity.acquire.cta.shared::cta.b64 p, [%1], %2;\n\t"
      "selp.b32 %0, 1, 0, p;\n\t}"
      : "=r"(done) : "r"(bar), "r"(parity) : "memory");
  if (!done) {
    asm volatile(
        "{\n\t.reg .pred P1;\n\t"
        "W_%=:\n\t"
        "mbarrier.try_wait.parity.acquire.cta.shared::cta.b64 P1, [%0], %1, 0x989680;\n\t"
        "@P1 bra.uni D_%=;\n\t"
        "bra.uni W_%=;\n\t"
        "D_%=:\n\t}"
        :: "r"(bar), "r"(parity) : "memory");
  }
}
__device__ __forceinline__ void tma3d(uint32_t dst, const CUtensorMap* map,
                                      int x, int y, int z, uint32_t bar) {
  asm volatile(
      "cp.async.bulk.tensor.3d.shared::cta.global.tile.mbarrier::complete_tx::bytes "
      "[%0], [%1, {%2, %3, %4}], [%5];"
      :: "r"(dst), "l"(map), "r"(x), "r"(y), "r"(z), "r"(bar) : "memory");
}
__device__ __forceinline__ void tma3d_store(const CUtensorMap* map,
                                            int x, int y, int z, uint32_t src) {
  asm volatile(
      "cp.async.bulk.tensor.3d.global.shared::cta.tile.bulk_group "
      "[%0, {%1, %2, %3}], [%4];"
      :: "l"(map), "r"(x), "r"(y), "r"(z), "r"(src) : "memory");
}

}  // namespace

// fragment-ordered mask: [win][warp(4)][j(8)][lane(32)][4 floats]
__device__ float g_maskf[576 * 4096];

__global__ void repack_mask(const float* __restrict__ mask) {
  const int win = blockIdx.x;
  const int tid = threadIdx.x;
  const int wid = tid >> 5;
  const int lid = tid & 31;
  const int g = lid >> 2;
  const int t = lid & 3;
  const float* __restrict__ src = mask + win * 4096;
  float* __restrict__ dst = g_maskf + win * 4096 + wid * 1024;
#pragma unroll
  for (int j = 0; j < 8; j++) {
    const int c0 = 8 * j + 2 * t;
    float4 m;
    m.x = src[(wid * 16 + g) * 64 + c0];
    m.y = src[(wid * 16 + g) * 64 + c0 + 1];
    m.z = src[(wid * 16 + 8 + g) * 64 + c0];
    m.w = src[(wid * 16 + 8 + g) * 64 + c0 + 1];
    *(float4*)(dst + j * 128 + lid * 4) = m;
  }
}

__global__ __launch_bounds__(128, 6) void winattn_tma6(
    const __grid_constant__ CUtensorMap mapQ,
    const __grid_constant__ CUtensorMap mapKV,
    const __grid_constant__ CUtensorMap mapO) {
  extern __shared__ float dyn[];
  float* __restrict__ raw = dyn + RAW;
  uint32_t* __restrict__ sm = (uint32_t*)dyn;   // tiles addressed by absolute word offset

  const int tid = threadIdx.x;
  const int wid = tid >> 5;
  const int lid = tid & 31;

  // block decode: 48 consecutive CTAs (8 b x 6 d) share one mask window (L2 reuse)
  const int blk = blockIdx.x;
  const int win = blk / 48;
  const int rem = blk % 48;
  const int b = rem / 6;
  const int d = rem % 6;
  const int u = win / 24;
  const int v = win % 24;
  const int zc = b * 192 + d * 32;

  const uint32_t mbar = s2u(dyn + MBAR);
  const uint32_t rawA = s2u(raw);
  if (tid == 0) bar_init(mbar, 1);
  __syncthreads();

  // ---------------- phase 1: Q -> raw, convert to TQH/TQL ----------------
  if (tid == 0) {
    bar_expect(mbar, 8192);
    tma3d(rawA, &mapQ, v * 8, u * 8, zc, mbar);
  }
  bar_wait(mbar, 0);
#pragma unroll
  for (int it = 0; it < 2; it++) {
    const int p  = it * 128 + tid;       // 0..255
    const int cw = p >> 4;               // word index = ci/2 (0..15)
    const int h  = (p >> 1) & 7;
    const int wq = p & 1;
    const int n0 = h * 8 + wq * 4;
    const int ro = (2 * cw) * 64 + h * 8 + wq * 4;
    const float4 a0 = *(const float4*)(raw + ro);
    const float4 a1 = *(const float4*)(raw + ro + 64);
#pragma unroll
    for (int j = 0; j < 4; j++) {
      const float f0 = felem(a0, j), f1 = felem(a1, j);
      const int w = qkw(n0 + j, cw);
      sm[TQH + w] = pack2(f0, f1);
      sm[TQL + w] = pack2(f0 - bfv(f0), f1 - bfv(f1));
    }
  }
  __syncthreads();

  // ---------------- phase 2: K -> raw, convert to TKH/TKL ----------------
  if (tid == 0) {
    bar_expect(mbar, 8192);
    tma3d(rawA, &mapKV, v * 8, u * 8, zc, mbar);
  }
  bar_wait(mbar, 1);
#pragma unroll
  for (int it = 0; it < 2; it++) {
    const int p  = it * 128 + tid;
    const int cw = p >> 4;
    const int h  = (p >> 1) & 7;
    const int wq = p & 1;
    const int n0 = h * 8 + wq * 4;
    const int ro = (2 * cw) * 64 + h * 8 + wq * 4;
    const float4 a0 = *(const float4*)(raw + ro);
    const float4 a1 = *(const float4*)(raw + ro + 64);
#pragma unroll
    for (int j = 0; j < 4; j++) {
      const float f0 = felem(a0, j), f1 = felem(a1, j);
      const int w = qkw(n0 + j, cw);
      sm[TKH + w] = pack2(f0, f1);
      sm[TKL + w] = pack2(f0 - bfv(f0), f1 - bfv(f1));
    }
  }
  __syncthreads();

  // ---------------- phase 3: V -> raw, convert to TVH/TVL ----------------
  if (tid == 0) {
    bar_expect(mbar, 8192);
    tma3d(rawA, &mapKV, v * 8, u * 8, 1536 + zc, mbar);
  }
  bar_wait(mbar, 0);
#pragma unroll
  for (int it = 0; it < 4; it++) {
    const int p  = it * 128 + tid;       // 0..511
    const int ci = p >> 4;
    const int h  = (p >> 1) & 7;
    const int wq = p & 1;
    const int n0 = h * 8 + wq * 4;
    const float4 a = *(const float4*)(raw + ci * 64 + h * 8 + wq * 4);
    uint2 hp, lp;
    hp.x = pack2(a.x, a.y);
    hp.y = pack2(a.z, a.w);
    lp.x = pack2(a.x - bfv(a.x), a.y - bfv(a.y));
    lp.y = pack2(a.z - bfv(a.z), a.w - bfv(a.w));
    *(uint2*)&sm[TVH + ci * 36 + (n0 >> 1)] = hp;
    *(uint2*)&sm[TVL + ci * 36 + (n0 >> 1)] = lp;
  }
  __syncthreads();

  const int g  = lid >> 2;   // 0..7
  const int t  = lid & 3;    // 0..3
  const int m0 = wid * 16;

  // ================= A-fragments =================================================
  uint32_t aqh[2][4], aql[2][4];
#pragma unroll
  for (int ks = 0; ks < 2; ks++) {
    aqh[ks][0] = sm[TQH + qkw(m0 + g,     ks * 8 + t)];
    aqh[ks][1] = sm[TQH + qkw(m0 + g + 8, ks * 8 + t)];
    aqh[ks][2] = sm[TQH + qkw(m0 + g,     ks * 8 + 4 + t)];
    aqh[ks][3] = sm[TQH + qkw(m0 + g + 8, ks * 8 + 4 + t)];
    aql[ks][0] = sm[TQL + qkw(m0 + g,     ks * 8 + t)];
    aql[ks][1] = sm[TQL + qkw(m0 + g + 8, ks * 8 + t)];
    aql[ks][2] = sm[TQL + qkw(m0 + g,     ks * 8 + 4 + t)];
    aql[ks][3] = sm[TQL + qkw(m0 + g + 8, ks * 8 + 4 + t)];
  }

  // ================= QK^T : warp owns rows m0..m0+15 =============================
  float c[8][4];
#pragma unroll
  for (int j = 0; j < 8; j++)
#pragma unroll
    for (int i = 0; i < 4; i++) c[j][i] = 0.f;

#pragma unroll
  for (int j = 0; j < 8; j++) {          // n-tile: cols 8j..8j+7
    const int rb = j * 8 + g;
#pragma unroll
    for (int ks = 0; ks < 2; ks++) {
      const uint32_t bh0 = sm[TKH + qkw(rb, ks * 8 + t)];
      const uint32_t bh1 = sm[TKH + qkw(rb, ks * 8 + 4 + t)];
      const uint32_t bl0 = sm[TKL + qkw(rb, ks * 8 + t)];
      const uint32_t bl1 = sm[TKL + qkw(rb, ks * 8 + 4 + t)];
      mma_bf16(c[j], aqh[ks], bh0, bh1);
      mma_bf16(c[j], aqh[ks], bl0, bl1);
      mma_bf16(c[j], aql[ks], bh0, bh1);
    }
  }

  // ===== softmax: mask from fragment-ordered global buffer (dense LDG.128) ======
  const float4* __restrict__ mw =
      (const float4*)(g_maskf + win * 4096 + wid * 1024) + lid;
  float sum0 = 0.f, sum1 = 0.f;
#pragma unroll
  for (int j = 0; j < 8; j++) {
    const float4 m = mw[j * 32];
    float e;
    e = __expf(fmaf(c[j][0], SCALE, m.x)); c[j][0] = e; sum0 += e;
    e = __expf(fmaf(c[j][1], SCALE, m.y)); c[j][1] = e; sum0 += e;
    e = __expf(fmaf(c[j][2], SCALE, m.z)); c[j][2] = e; sum1 += e;
    e = __expf(fmaf(c[j][3], SCALE, m.w)); c[j][3] = e; sum1 += e;
  }
  sum0 += __shfl_xor_sync(0xffffffffu, sum0, 1);
  sum0 += __shfl_xor_sync(0xffffffffu, sum0, 2);
  sum1 += __shfl_xor_sync(0xffffffffu, sum1, 1);
  sum1 += __shfl_xor_sync(0xffffffffu, sum1, 2);
  const float inv0 = 1.0f / sum0;
  const float inv1 = 1.0f / sum1;

  // P fragments (S accumulator layout == PV A-fragment layout), hi/lo split
  uint32_t aph[4][4], apl[4][4];
#pragma unroll
  for (int ks = 0; ks < 4; ks++) {
    const float* p0 = c[2 * ks];
    const float* p1 = c[2 * ks + 1];
    aph[ks][0] = pack2(p0[0], p0[1]);
    aph[ks][1] = pack2(p0[2], p0[3]);
    aph[ks][2] = pack2(p1[0], p1[1]);
    aph[ks][3] = pack2(p1[2], p1[3]);
    apl[ks][0] = pack2(p0[0] - bfv(p0[0]), p0[1] - bfv(p0[1]));
    apl[ks][1] = pack2(p0[2] - bfv(p0[2]), p0[3] - bfv(p0[3]));
    apl[ks][2] = pack2(p1[0] - bfv(p1[0]), p1[1] - bfv(p1[1]));
    apl[ks][3] = pack2(p1[2] - bfv(p1[2]), p1[3] - bfv(p1[3]));
  }
  __syncthreads();   // all warps past tile reads before sO overwrites Q region

  // ================= O = P V =====================================================
  float o[4][4];
#pragma unroll
  for (int jn = 0; jn < 4; jn++)
#pragma unroll
    for (int i = 0; i < 4; i++) o[jn][i] = 0.f;

#pragma unroll
  for (int jn = 0; jn < 4; jn++) {       // channel tile 8jn..8jn+7
    const int rv = (jn * 8 + g) * 36;
#pragma unroll
    for (int ks = 0; ks < 4; ks++) {     // key step 16ks..16ks+15
      const uint32_t bh0 = sm[TVH + rv + ks * 8 + t];
      const uint32_t bh1 = sm[TVH + rv + ks * 8 + 4 + t];
      const uint32_t bl0 = sm[TVL + rv + ks * 8 + t];
      const uint32_t bl1 = sm[TVL + rv + ks * 8 + 4 + t];
      mma_bf16(o[jn], aph[ks], bh0, bh1);
      mma_bf16(o[jn], aph[ks], bl0, bl1);
      mma_bf16(o[jn], apl[ks], bh0, bh1);
    }
  }

  // ===== stage O dense [c][h][w] fp32 (plain layout, TMA store source) ===========
  float* __restrict__ sO = dyn + TQH;    // words [2048..4096), Q tiles dead
#pragma unroll
  for (int jn = 0; jn < 4; jn++) {
    const int ch = jn * 8 + 2 * t;
#pragma unroll
    for (int bb = 0; bb < 2; bb++) {
      sO[(ch + bb) * 64 + m0 + g]     = o[jn][bb] * inv0;
      sO[(ch + bb) * 64 + m0 + g + 8] = o[jn][2 + bb] * inv1;
    }
  }
  __syncthreads();

  // ================= TMA store O =================================================
  if (tid == 0) {
    asm volatile("fence.proxy.async.shared::cta;" ::: "memory");
    tma3d_store(&mapO, v * 8, u * 8, zc, s2u(sO));
    asm volatile("cp.async.bulk.commit_group;" ::: "memory");
    asm volatile("cp.async.bulk.wait_group 0;" ::: "memory");
  }
}

typedef CUresult (*EncodeFn)(CUtensorMap*, CUtensorMapDataType, cuuint32_t, void*,
                             const cuuint64_t*, const cuuint64_t*, const cuuint32_t*,
                             const cuuint32_t*, CUtensorMapInterleave, CUtensorMapSwizzle,
                             CUtensorMapL2promotion, CUtensorMapFloatOOBfill);

extern "C" void kernel_launch(void* const* d_in, const int* in_sizes, int n_in,
                              void* d_out, int out_size) {
  const float* kv = nullptr;
  const float* q = nullptr;
  const float* mask = nullptr;
  for (int i = 0; i < n_in; i++) {
    if (in_sizes[i] == 113246208) kv = (const float*)d_in[i];
    else if (in_sizes[i] == 56623104) q = (const float*)d_in[i];
    else if (in_sizes[i] == 2359296) mask = (const float*)d_in[i];
  }
  if (!kv)   kv   = (const float*)d_in[0];
  if (!q)    q    = (const float*)d_in[1];
  if (!mask) mask = (const float*)d_in[2];

  EncodeFn encode = nullptr;
  cudaDriverEntryPointQueryResult qres;
  cudaGetDriverEntryPoint("cuTensorMapEncodeTiled", (void**)&encode,
                          cudaEnableDefault, &qres);

  cuuint64_t strides[2] = {192 * 4ull, (cuuint64_t)HW * 4ull};
  cuuint32_t box[3]     = {8, 8, 32};
  cuuint32_t es[3]      = {1, 1, 1};

  CUtensorMap mapQ{}, mapKV{}, mapO{};
  {
    cuuint64_t dims[3] = {192, 192, 1536};
    encode(&mapQ, CU_TENSOR_MAP_DATA_TYPE_FLOAT32, 3, (void*)q,
           dims, strides, box, es,
           CU_TENSOR_MAP_INTERLEAVE_NONE, CU_TENSOR_MAP_SWIZZLE_NONE,
           CU_TENSOR_MAP_L2_PROMOTION_L2_128B, CU_TENSOR_MAP_FLOAT_OOB_FILL_NONE);
  }
  {
    cuuint64_t dims[3] = {192, 192, 3072};
    encode(&mapKV, CU_TENSOR_MAP_DATA_TYPE_FLOAT32, 3, (void*)kv,
           dims, strides, box, es,
           CU_TENSOR_MAP_INTERLEAVE_NONE, CU_TENSOR_MAP_SWIZZLE_NONE,
           CU_TENSOR_MAP_L2_PROMOTION_L2_128B, CU_TENSOR_MAP_FLOAT_OOB_FILL_NONE);
  }
  {
    cuuint64_t dims[3] = {192, 192, 1536};
    encode(&mapO, CU_TENSOR_MAP_DATA_TYPE_FLOAT32, 3, d_out,
           dims, strides, box, es,
           CU_TENSOR_MAP_INTERLEAVE_NONE, CU_TENSOR_MAP_SWIZZLE_NONE,
           CU_TENSOR_MAP_L2_PROMOTION_L2_128B, CU_TENSOR_MAP_FLOAT_OOB_FILL_NONE);
  }

  repack_mask<<<576, 128>>>(mask);
  cudaFuncSetAttribute(winattn_tma6, cudaFuncAttributeMaxDynamicSharedMemorySize,
                       SMEM_BYTES);
  winattn_tma6<<<27648, 128, SMEM_BYTES>>>(mapQ, mapKV, mapO);
}